// round 1
// baseline (speedup 1.0000x reference)
#include <cuda_runtime.h>
#include <cuda_bf16.h>

// Problem constants (fixed shapes from reference setup_inputs)
constexpr int B   = 4;
constexpr int N   = 4096;   // anchors per batch
constexpr int M   = 4096;   // neighbors per batch
constexpr int C   = 128;    // channels
constexpr int KNN = 32;     // k
constexpr float R2 = 0.12f * 0.12f;

// Scratch (allocation-free rule: __device__ globals)
__device__ float g_QA[B * N * C];   // (anchor@Wq + bq - bk)@Wa + ba
__device__ float g_AD[B * N * C];   // anchor@Wd + bd
__device__ float g_KA[B * M * C];   // (neighbor@Wk)@Wa
__device__ float g_ND[B * M * C];   // neighbor@Wd
__device__ int   g_idx[B * N * KNN];

// ---------------------------------------------------------------------------
// Projection kernel: one block (C=128 threads) per point row.
//   ANCHOR path:  q = xyz@Wq + (bq - bk);  outA = q@Wa + ba;  outD = xyz@Wd + bd
//   NEIGHBOR:     q = xyz@Wk;              outA = q@Wa;       outD = xyz@Wd
// ---------------------------------------------------------------------------
template <bool ANCHOR>
__global__ void proj_kernel(const float* __restrict__ xyz,
                            const float* __restrict__ W1,   // Wq or Wk, [3][C]
                            const float* __restrict__ bq,
                            const float* __restrict__ bk,
                            const float* __restrict__ Wa,   // [C][C]
                            const float* __restrict__ ba,
                            const float* __restrict__ Wd,   // [3][C]
                            const float* __restrict__ bd)
{
    __shared__ float q_s[C];
    const int row = blockIdx.x;
    const int c   = threadIdx.x;

    const float x = xyz[row * 3 + 0];
    const float y = xyz[row * 3 + 1];
    const float z = xyz[row * 3 + 2];

    float q = x * W1[c] + y * W1[C + c] + z * W1[2 * C + c];
    if (ANCHOR) q += bq[c] - bk[c];
    q_s[c] = q;

    float d = x * Wd[c] + y * Wd[C + c] + z * Wd[2 * C + c];
    if (ANCHOR) d += bd[c];

    float* outA = ANCHOR ? g_QA : g_KA;
    float* outD = ANCHOR ? g_AD : g_ND;
    outD[(size_t)row * C + c] = d;

    __syncthreads();

    float acc = ANCHOR ? ba[c] : 0.0f;
#pragma unroll 16
    for (int cc = 0; cc < C; ++cc)
        acc += q_s[cc] * Wa[cc * C + c];
    outA[(size_t)row * C + c] = acc;
}

// ---------------------------------------------------------------------------
// Ball query: warp per anchor, ordered scan over M neighbors, first KNN hits.
// Block = 256 threads = 8 anchors. Neighbor xyz staged in shared in 1024-pt
// tiles (coalesced load; strided LDS with stride 3 -> conflict-free).
// ---------------------------------------------------------------------------
__global__ void ballquery_kernel(const float* __restrict__ anchor,
                                 const float* __restrict__ neighbor)
{
    constexpr int TILE = 1024;
    __shared__ float tile[TILE * 3];

    const int warp = threadIdx.x >> 5;
    const int lane = threadIdx.x & 31;
    const int row  = blockIdx.x * 8 + warp;      // global anchor row
    const int b    = row >> 12;                  // row / N

    const float ax = anchor[row * 3 + 0];
    const float ay = anchor[row * 3 + 1];
    const float az = anchor[row * 3 + 2];

    const float* nb = neighbor + (size_t)b * M * 3;

    int cnt = 0;
    int first = 0;

    for (int t = 0; t < M; t += TILE) {
        __syncthreads();
        for (int i = threadIdx.x; i < TILE * 3; i += blockDim.x)
            tile[i] = nb[(size_t)t * 3 + i];
        __syncthreads();

        if (cnt >= KNN) continue;

        for (int j = 0; j < TILE; j += 32) {
            const int ml = j + lane;
            const float dx = tile[3 * ml + 0] - ax;
            const float dy = tile[3 * ml + 1] - ay;
            const float dz = tile[3 * ml + 2] - az;
            const bool pred = (dx * dx + dy * dy + dz * dz) < R2;
            const unsigned mask = __ballot_sync(0xffffffffu, pred);
            if (mask) {
                if (cnt == 0) first = t + j + __ffs(mask) - 1;
                if (pred) {
                    const int pos = cnt + __popc(mask & ((1u << lane) - 1u));
                    if (pos < KNN) g_idx[(size_t)row * KNN + pos] = t + ml;
                }
                cnt += __popc(mask);
                if (cnt >= KNN) break;
            }
        }
    }

    // Pad slots [cnt, KNN): first found index, or 0 if none found
    // (matches pointnet2 / reference argsort semantics).
    const int ccap = cnt < KNN ? cnt : KNN;
    if (lane >= ccap)
        g_idx[(size_t)row * KNN + lane] = (cnt > 0) ? first : 0;
}

// ---------------------------------------------------------------------------
// Attention: warp per anchor, lane holds channels [4*lane, 4*lane+4).
// Per k: gather KA/ND rows (float4, coalesced 512B), logits = QA - KA,
// softmax over C via warp xor-shuffle reductions, out = max_k(dis * w).
// ---------------------------------------------------------------------------
__global__ void attn_kernel(float* __restrict__ out)
{
    const unsigned FULL = 0xffffffffu;
    const int warp = threadIdx.x >> 5;
    const int lane = threadIdx.x & 31;
    const int row  = blockIdx.x * 8 + warp;
    const int b    = row >> 12;

    const float4 qa = *(const float4*)(g_QA + (size_t)row * C + lane * 4);
    const float4 ad = *(const float4*)(g_AD + (size_t)row * C + lane * 4);
    const int my_m  = g_idx[(size_t)row * KNN + lane];

    const float* KAb = g_KA + (size_t)b * M * C;
    const float* NDb = g_ND + (size_t)b * M * C;

    float4 o = make_float4(-3.4e38f, -3.4e38f, -3.4e38f, -3.4e38f);

#pragma unroll 4
    for (int k = 0; k < KNN; ++k) {
        const int m = __shfl_sync(FULL, my_m, k);
        const float4 kv = *(const float4*)(KAb + (size_t)m * C + lane * 4);
        const float4 nv = *(const float4*)(NDb + (size_t)m * C + lane * 4);

        const float l0 = qa.x - kv.x;
        const float l1 = qa.y - kv.y;
        const float l2 = qa.z - kv.z;
        const float l3 = qa.w - kv.w;

        float mx = fmaxf(fmaxf(l0, l1), fmaxf(l2, l3));
#pragma unroll
        for (int off = 16; off; off >>= 1)
            mx = fmaxf(mx, __shfl_xor_sync(FULL, mx, off));

        const float e0 = __expf(l0 - mx);
        const float e1 = __expf(l1 - mx);
        const float e2 = __expf(l2 - mx);
        const float e3 = __expf(l3 - mx);

        float s = (e0 + e1) + (e2 + e3);
#pragma unroll
        for (int off = 16; off; off >>= 1)
            s += __shfl_xor_sync(FULL, s, off);

        const float inv = 1.0f / s;
        o.x = fmaxf(o.x, (ad.x - nv.x) * (e0 * inv));
        o.y = fmaxf(o.y, (ad.y - nv.y) * (e1 * inv));
        o.z = fmaxf(o.z, (ad.z - nv.z) * (e2 * inv));
        o.w = fmaxf(o.w, (ad.w - nv.w) * (e3 * inv));
    }

    *(float4*)(out + (size_t)row * C + lane * 4) = o;
}

// ---------------------------------------------------------------------------
extern "C" void kernel_launch(void* const* d_in, const int* in_sizes, int n_in,
                              void* d_out, int out_size)
{
    const float* anchor   = (const float*)d_in[0];  // (B,N,3)
    const float* neighbor = (const float*)d_in[1];  // (B,M,3)
    const float* Wq = (const float*)d_in[2];
    const float* bq = (const float*)d_in[3];
    const float* Wk = (const float*)d_in[4];
    const float* bk = (const float*)d_in[5];
    const float* Wd = (const float*)d_in[6];
    const float* bd = (const float*)d_in[7];
    const float* Wa = (const float*)d_in[8];
    const float* ba = (const float*)d_in[9];
    float* out = (float*)d_out;                     // (B,N,C)

    proj_kernel<true ><<<B * N, C>>>(anchor,   Wq, bq, bk, Wa, ba, Wd, bd);
    proj_kernel<false><<<B * M, C>>>(neighbor, Wk, bq, bk, Wa, ba, Wd, bd);
    ballquery_kernel<<<(B * N) / 8, 256>>>(anchor, neighbor);
    attn_kernel<<<(B * N) / 8, 256>>>(out);
}

// round 3
// speedup vs baseline: 1.3225x; 1.3225x over previous
#include <cuda_runtime.h>
#include <cuda_bf16.h>

// ---------------------------------------------------------------------------
// Problem constants (fixed shapes)
constexpr int B    = 4;
constexpr int NPTS = 4096;   // anchors per batch
constexpr int MPTS = 4096;   // neighbors per batch
constexpr int C    = 128;
constexpr int KNN  = 32;
constexpr float RAD2 = 0.12f * 0.12f;
constexpr int GC   = 8;          // grid cells per dim (cell 0.125 > r 0.12)
constexpr int NC   = GC*GC*GC;   // 512 cells per batch

// Scratch (__device__ globals; allocation-free rule)
__device__ __align__(16) float g_QA[B*NPTS*C];  // (a@Wq + bq - bk)@Wa + ba
__device__ __align__(16) float g_AD[B*NPTS*C];  // a@Wd + bd
__device__ __align__(16) float g_KA[B*MPTS*C];  // (n@Wk)@Wa
__device__ __align__(16) float g_ND[B*MPTS*C];  // n@Wd
__device__ int g_idx[B*NPTS*KNN];

// Spatial grid: set 0 = anchors, set 1 = neighbors.
__device__ int g_cnt  [2*B*NC];
__device__ int g_start[2*B*NC];
__device__ int g_cur  [2*B*NC];
__device__ int g_list [2*B*4096];   // local point idx, grouped by cell

// f32x2 packed FMA (SASS FFMA2 — 2x fp32 rate; only reachable via PTX)
#define FFMA2(d, a, b, c) \
    asm("fma.rn.f32x2 %0, %1, %2, %3;" : "=l"(d) : "l"(a), "l"(b), "l"(c))
#define PACKF2(d, lo, hi) \
    asm("mov.b64 %0, {%1, %2};" : "=l"(d) : "f"(lo), "f"(hi))

__device__ __forceinline__ void cell_coords(float x, float y, float z,
                                            int& cx, int& cy, int& cz) {
    cx = min(GC-1, max(0, (int)(x * (float)GC)));
    cy = min(GC-1, max(0, (int)(y * (float)GC)));
    cz = min(GC-1, max(0, (int)(z * (float)GC)));
}

// ---------------------------------------------------------------------------
// Grid build
// ---------------------------------------------------------------------------
__global__ void zero_kernel() {
    int i = blockIdx.x * blockDim.x + threadIdx.x;
    if (i < 2*B*NC) g_cnt[i] = 0;
}

__global__ void count_kernel(const float* __restrict__ anchor,
                             const float* __restrict__ neighbor) {
    int i = blockIdx.x * blockDim.x + threadIdx.x;
    if (i >= 2*B*4096) return;
    int set = i >> 14;          // 0 anchors, 1 neighbors
    int loc = i & 16383;        // b*4096 + local
    int b   = loc >> 12;
    const float* p = (set ? neighbor : anchor) + (size_t)loc * 3;
    int cx, cy, cz; cell_coords(p[0], p[1], p[2], cx, cy, cz);
    atomicAdd(&g_cnt[set*(B*NC) + b*NC + cz*64 + cy*8 + cx], 1);
}

__global__ void scan_kernel() {   // one block per (set,batch): 8 blocks of 512
    __shared__ int s[NC];
    int t = threadIdx.x;
    int base = blockIdx.x * NC;
    int c = g_cnt[base + t];
    s[t] = c;
    __syncthreads();
    for (int off = 1; off < NC; off <<= 1) {
        int v = (t >= off) ? s[t - off] : 0;
        __syncthreads();
        s[t] += v;
        __syncthreads();
    }
    int start = s[t] - c;       // exclusive
    g_start[base + t] = start;
    g_cur  [base + t] = start;
}

__global__ void scatter_kernel(const float* __restrict__ anchor,
                               const float* __restrict__ neighbor) {
    int i = blockIdx.x * blockDim.x + threadIdx.x;
    if (i >= 2*B*4096) return;
    int set = i >> 14;
    int loc = i & 16383;
    int b   = loc >> 12;
    int pid = loc & 4095;
    const float* p = (set ? neighbor : anchor) + (size_t)loc * 3;
    int cx, cy, cz; cell_coords(p[0], p[1], p[2], cx, cy, cz);
    int slot = atomicAdd(&g_cur[set*(B*NC) + b*NC + cz*64 + cy*8 + cx], 1);
    g_list[set*(B*4096) + b*4096 + slot] = pid;
}

// ---------------------------------------------------------------------------
// Fused projections. Blocks [0,1024): anchors, [1024,2048): neighbors.
// 16 rows per block (128 threads). Phase A: tiny 3->C projections into smem +
// direct D-path stores. Phase B: (16 x 128)@(128 x 128) GEMM, warp = 4 rows,
// lane = 4 output channels (one ulonglong2 = 16B per Wa row), FFMA2 accumulate.
// ---------------------------------------------------------------------------
__global__ void proj_kernel(const float* __restrict__ anchor,
                            const float* __restrict__ neighbor,
                            const float* __restrict__ Wq,
                            const float* __restrict__ bq,
                            const float* __restrict__ Wk,
                            const float* __restrict__ bk,
                            const float* __restrict__ Wd,
                            const float* __restrict__ bd,
                            const float* __restrict__ Wa,
                            const float* __restrict__ ba)
{
    constexpr int TR = 16;
    __shared__ float q_s[TR * C];
    __shared__ float p_s[TR * 3];

    const bool AN = blockIdx.x < 1024;
    const int  base_row = (AN ? blockIdx.x : blockIdx.x - 1024) * TR;
    const float* xyz = AN ? anchor : neighbor;
    const int t = threadIdx.x;

    if (t < TR * 3) p_s[t] = xyz[(size_t)base_row * 3 + t];
    __syncthreads();

    // Phase A: q = xyz@W1 (+bq-bk), d = xyz@Wd (+bd)
    {
        const float* W1 = AN ? Wq : Wk;
        const float w1x = W1[t], w1y = W1[C + t], w1z = W1[2*C + t];
        const float wdx = Wd[t], wdy = Wd[C + t], wdz = Wd[2*C + t];
        const float qb = AN ? (bq[t] - bk[t]) : 0.0f;
        const float db = AN ? bd[t] : 0.0f;
        float* outD = AN ? g_AD : g_ND;
#pragma unroll
        for (int r = 0; r < TR; ++r) {
            const float x = p_s[r*3], y = p_s[r*3+1], z = p_s[r*3+2];
            q_s[r*C + t] = qb + x*w1x + y*w1y + z*w1z;
            outD[(size_t)(base_row + r) * C + t] = db + x*wdx + y*wdy + z*wdz;
        }
    }
    __syncthreads();

    // Phase B
    const int w = t >> 5, lane = t & 31;
    unsigned long long acc[4][2];
    if (AN) {
        const float4 bav = ((const float4*)ba)[lane];
#pragma unroll
        for (int r = 0; r < 4; ++r) {
            PACKF2(acc[r][0], bav.x, bav.y);
            PACKF2(acc[r][1], bav.z, bav.w);
        }
    } else {
#pragma unroll
        for (int r = 0; r < 4; ++r) { acc[r][0] = 0ull; acc[r][1] = 0ull; }
    }

    // Wa row cc = 128 floats = 32 ulonglong2; lane owns ulonglong2 #lane
    // (channels 4*lane .. 4*lane+3).
    const ulonglong2* WaV = (const ulonglong2*)Wa;
    const float* qrow = q_s + (w * 4) * C;
#pragma unroll 4
    for (int cc = 0; cc < C; ++cc) {
        const ulonglong2 wv = WaV[cc * 32 + lane];
#pragma unroll
        for (int r = 0; r < 4; ++r) {
            const float q = qrow[r * C + cc];
            unsigned long long qq; PACKF2(qq, q, q);
            FFMA2(acc[r][0], qq, wv.x, acc[r][0]);
            FFMA2(acc[r][1], qq, wv.y, acc[r][1]);
        }
    }

    float* outA = AN ? g_QA : g_KA;
#pragma unroll
    for (int r = 0; r < 4; ++r) {
        ulonglong2 st; st.x = acc[r][0]; st.y = acc[r][1];
        ((ulonglong2*)(outA + (size_t)(base_row + w*4 + r) * C))[lane] = st;
    }
}

// ---------------------------------------------------------------------------
// Ball query via grid. Warp per anchor (cell-sorted order). Collect all hits
// from the 27 neighboring cells into a per-warp buffer, then warp rank-sort
// (pairwise '<' counts) to emit the first-KNN-by-original-index semantics.
// ---------------------------------------------------------------------------
__global__ void ballquery_kernel(const float* __restrict__ anchor,
                                 const float* __restrict__ neighbor)
{
    constexpr unsigned FULL = 0xffffffffu;
    constexpr int CAP = 128;
    __shared__ int hbuf[8][CAP];
    __shared__ int sorted[8][KNN];

    const int warp = threadIdx.x >> 5;
    const int lane = threadIdx.x & 31;
    const int p    = blockIdx.x * 8 + warp;       // cell-sorted anchor position
    const int b    = p >> 12;
    const int row  = (b << 12) + g_list[p];       // set 0 region

    const float ax = anchor[(size_t)row*3 + 0];
    const float ay = anchor[(size_t)row*3 + 1];
    const float az = anchor[(size_t)row*3 + 2];
    int cx, cy, cz; cell_coords(ax, ay, az, cx, cy, cz);

    const int nbase  = B*NC + b*NC;               // g_cnt/g_start neighbor region
    const int lbase  = B*4096 + b*4096;           // g_list neighbor region
    const float* nb  = neighbor + (size_t)b * MPTS * 3;

    int hcnt = 0;
    for (int dz = -1; dz <= 1; ++dz) {
        const int z = cz + dz; if ((unsigned)z >= (unsigned)GC) continue;
        for (int dy = -1; dy <= 1; ++dy) {
            const int y = cy + dy; if ((unsigned)y >= (unsigned)GC) continue;
            for (int dx = -1; dx <= 1; ++dx) {
                const int x = cx + dx; if ((unsigned)x >= (unsigned)GC) continue;
                const int cidx = nbase + z*64 + y*8 + x;
                const int st = g_start[cidx];
                const int cn = g_cnt[cidx];
                for (int j = 0; j < cn; j += 32) {
                    const int q = j + lane;
                    int m = 0; bool hit = false;
                    if (q < cn) {
                        m = g_list[lbase + st + q];
                        const float fx = nb[m*3+0] - ax;
                        const float fy = nb[m*3+1] - ay;
                        const float fz = nb[m*3+2] - az;
                        hit = (fx*fx + fy*fy + fz*fz) < RAD2;
                    }
                    const unsigned mk = __ballot_sync(FULL, hit);
                    if (hit) {
                        const int pos = hcnt + __popc(mk & ((1u << lane) - 1u));
                        if (pos < CAP) hbuf[warp][pos] = m;
                    }
                    hcnt += __popc(mk);
                }
            }
        }
    }

    __syncwarp(FULL);
    const int n = min(hcnt, CAP);
    const int rounds = (n + 31) >> 5;

    int v[4], rk[4];
#pragma unroll
    for (int r = 0; r < 4; ++r) {
        const int i = lane + 32*r;
        v[r]  = (i < n) ? hbuf[warp][i] : 0x7fffffff;
        rk[r] = 0;
    }
    for (int step = 0; step < 32; ++step) {
#pragma unroll
        for (int s = 0; s < 4; ++s) {
            if (s < rounds) {
                const int u = __shfl_sync(FULL, v[s], step);
#pragma unroll
                for (int r = 0; r < 4; ++r)
                    if (r < rounds) rk[r] += (u < v[r]);
            }
        }
    }
#pragma unroll
    for (int r = 0; r < 4; ++r) {
        const int i = lane + 32*r;
        if (i < n && rk[r] < KNN) sorted[warp][rk[r]] = v[r];
    }
    __syncwarp(FULL);

    const int take  = min(hcnt, KNN);
    const int first = (hcnt > 0) ? sorted[warp][0] : 0;
    g_idx[(size_t)row * KNN + lane] = (lane < take) ? sorted[warp][lane] : first;
}

// ---------------------------------------------------------------------------
// Attention. Warp per anchor (cell-sorted order for gather locality).
// Lane holds channels [4*lane, 4*lane+4). Softmax without max-shift
// (shift-invariant; |logit| <= ~65 so exp can't overflow fp32).
// ---------------------------------------------------------------------------
__global__ void attn_kernel(float* __restrict__ out)
{
    constexpr unsigned FULL = 0xffffffffu;
    const int warp = threadIdx.x >> 5;
    const int lane = threadIdx.x & 31;
    const int p    = blockIdx.x * 8 + warp;
    const int b    = p >> 12;
    const int row  = (b << 12) + g_list[p];

    const float4 qa = ((const float4*)(g_QA + (size_t)row * C))[lane];
    const float4 ad = ((const float4*)(g_AD + (size_t)row * C))[lane];
    const int my_m  = g_idx[(size_t)row * KNN + lane];

    const float4* KA4 = (const float4*)(g_KA + (size_t)b * MPTS * C);
    const float4* ND4 = (const float4*)(g_ND + (size_t)b * MPTS * C);

    float4 o = make_float4(-3.4e38f, -3.4e38f, -3.4e38f, -3.4e38f);

#pragma unroll 4
    for (int k = 0; k < KNN; ++k) {
        const int m = __shfl_sync(FULL, my_m, k);
        const float4 kv = KA4[m * 32 + lane];
        const float4 nv = ND4[m * 32 + lane];

        const float e0 = __expf(qa.x - kv.x);
        const float e1 = __expf(qa.y - kv.y);
        const float e2 = __expf(qa.z - kv.z);
        const float e3 = __expf(qa.w - kv.w);

        float s = (e0 + e1) + (e2 + e3);
#pragma unroll
        for (int off = 16; off; off >>= 1)
            s += __shfl_xor_sync(FULL, s, off);

        const float inv = __fdividef(1.0f, s);
        o.x = fmaxf(o.x, (ad.x - nv.x) * (e0 * inv));
        o.y = fmaxf(o.y, (ad.y - nv.y) * (e1 * inv));
        o.z = fmaxf(o.z, (ad.z - nv.z) * (e2 * inv));
        o.w = fmaxf(o.w, (ad.w - nv.w) * (e3 * inv));
    }

    ((float4*)(out + (size_t)row * C))[lane] = o;
}

// ---------------------------------------------------------------------------
extern "C" void kernel_launch(void* const* d_in, const int* in_sizes, int n_in,
                              void* d_out, int out_size)
{
    const float* anchor   = (const float*)d_in[0];
    const float* neighbor = (const float*)d_in[1];
    const float* Wq = (const float*)d_in[2];
    const float* bq = (const float*)d_in[3];
    const float* Wk = (const float*)d_in[4];
    const float* bk = (const float*)d_in[5];
    const float* Wd = (const float*)d_in[6];
    const float* bd = (const float*)d_in[7];
    const float* Wa = (const float*)d_in[8];
    const float* ba = (const float*)d_in[9];
    float* out = (float*)d_out;

    zero_kernel   <<<8, 512>>>();
    count_kernel  <<<64, 512>>>(anchor, neighbor);
    scan_kernel   <<<8, 512>>>();
    scatter_kernel<<<64, 512>>>(anchor, neighbor);
    proj_kernel   <<<2048, 128>>>(anchor, neighbor, Wq, bq, Wk, bk, Wd, bd, Wa, ba);
    ballquery_kernel<<<2048, 256>>>(anchor, neighbor);
    attn_kernel   <<<2048, 256>>>(out);
}

// round 5
// speedup vs baseline: 1.7571x; 1.3287x over previous
#include <cuda_runtime.h>
#include <cuda_bf16.h>

// ---------------------------------------------------------------------------
// Problem constants (fixed shapes)
constexpr int B    = 4;
constexpr int NPTS = 4096;
constexpr int MPTS = 4096;
constexpr int C    = 128;
constexpr int KNN  = 32;
constexpr float RAD2 = 0.12f * 0.12f;
constexpr int GC   = 8;          // grid cells per dim (cell 0.125 > r 0.12)
constexpr int NC   = GC*GC*GC;   // 512 cells per batch

// Scratch (__device__ globals; allocation-free rule)
__device__ __align__(16) float g_QA[B*NPTS*C];  // (a@Wq + bq - bk)@Wa + ba
__device__ __align__(16) float g_AD[B*NPTS*C];  // a@Wd + bd
__device__ __align__(16) float g_KA[B*MPTS*C];  // (n@Wk)@Wa
__device__ __align__(16) float g_ND[B*MPTS*C];  // n@Wd
__device__ int g_idx[B*NPTS*KNN];

// Spatial grid: set 0 = anchors, set 1 = neighbors. Index = (set*4+b)*NC + cell.
__device__ int g_cnt  [2*B*NC];
__device__ int g_start[2*B*NC];
__device__ int g_list [2*B*4096];   // local point idx, grouped by cell

// f32x2 packed FMA (SASS FFMA2 — 2x fp32 rate; only reachable via PTX)
#define FFMA2(d, a, b, c) \
    asm("fma.rn.f32x2 %0, %1, %2, %3;" : "=l"(d) : "l"(a), "l"(b), "l"(c))
#define PACKF2(d, lo, hi) \
    asm("mov.b64 %0, {%1, %2};" : "=l"(d) : "f"(lo), "f"(hi))

__device__ __forceinline__ void cell_coords(float x, float y, float z,
                                            int& cx, int& cy, int& cz) {
    cx = min(GC-1, max(0, (int)(x * (float)GC)));
    cy = min(GC-1, max(0, (int)(y * (float)GC)));
    cz = min(GC-1, max(0, (int)(z * (float)GC)));
}

// ---------------------------------------------------------------------------
// Fused grid build: one block per (set, batch). 512 threads, 4096 points.
// smem count -> Hillis-Steele scan -> smem-atomic scatter. One launch.
// ---------------------------------------------------------------------------
__global__ void gridbuild_kernel(const float* __restrict__ anchor,
                                 const float* __restrict__ neighbor)
{
    __shared__ int s_cnt [NC];
    __shared__ int s_scan[NC];
    __shared__ int s_cur [NC];
    __shared__ int s_cell[4096];

    const int bi  = blockIdx.x;          // set*4 + b
    const int set = bi >> 2;
    const int b   = bi & 3;
    const float* pts = (set ? neighbor : anchor) + (size_t)b * 4096 * 3;
    const int t = threadIdx.x;

    s_cnt[t] = 0;
    __syncthreads();

#pragma unroll
    for (int r = 0; r < 8; ++r) {
        const int i = t + r * 512;
        const float x = pts[i*3], y = pts[i*3+1], z = pts[i*3+2];
        int cx, cy, cz; cell_coords(x, y, z, cx, cy, cz);
        const int c = cz*64 + cy*8 + cx;
        s_cell[i] = c;
        atomicAdd(&s_cnt[c], 1);
    }
    __syncthreads();

    const int cval = s_cnt[t];
    s_scan[t] = cval;
    __syncthreads();
    for (int off = 1; off < NC; off <<= 1) {
        const int v = (t >= off) ? s_scan[t - off] : 0;
        __syncthreads();
        s_scan[t] += v;
        __syncthreads();
    }
    const int start = s_scan[t] - cval;
    g_cnt  [bi*NC + t] = cval;
    g_start[bi*NC + t] = start;
    s_cur[t] = start;
    __syncthreads();

#pragma unroll
    for (int r = 0; r < 8; ++r) {
        const int i = t + r * 512;
        const int slot = atomicAdd(&s_cur[s_cell[i]], 1);
        g_list[bi*4096 + slot] = i;
    }
}

// ---------------------------------------------------------------------------
// Fused projections. Blocks [0,1024): anchors, [1024,2048): neighbors.
// 16 rows per block (128 threads). Phase A: tiny 3->C projections into smem +
// direct D-path stores. Phase B: (16 x 128)@(128 x 128) GEMM, warp = 4 rows,
// lane = 4 output channels (one ulonglong2 per Wa row), FFMA2 accumulate.
// ---------------------------------------------------------------------------
__global__ void proj_kernel(const float* __restrict__ anchor,
                            const float* __restrict__ neighbor,
                            const float* __restrict__ Wq,
                            const float* __restrict__ bq,
                            const float* __restrict__ Wk,
                            const float* __restrict__ bk,
                            const float* __restrict__ Wd,
                            const float* __restrict__ bd,
                            const float* __restrict__ Wa,
                            const float* __restrict__ ba)
{
    constexpr int TR = 16;
    __shared__ float q_s[TR * C];
    __shared__ float p_s[TR * 3];

    const bool AN = blockIdx.x < 1024;
    const int  base_row = (AN ? blockIdx.x : blockIdx.x - 1024) * TR;
    const float* xyz = AN ? anchor : neighbor;
    const int t = threadIdx.x;

    if (t < TR * 3) p_s[t] = xyz[(size_t)base_row * 3 + t];
    __syncthreads();

    {
        const float* W1 = AN ? Wq : Wk;
        const float w1x = W1[t], w1y = W1[C + t], w1z = W1[2*C + t];
        const float wdx = Wd[t], wdy = Wd[C + t], wdz = Wd[2*C + t];
        const float qb = AN ? (bq[t] - bk[t]) : 0.0f;
        const float db = AN ? bd[t] : 0.0f;
        float* outD = AN ? g_AD : g_ND;
#pragma unroll
        for (int r = 0; r < TR; ++r) {
            const float x = p_s[r*3], y = p_s[r*3+1], z = p_s[r*3+2];
            q_s[r*C + t] = qb + x*w1x + y*w1y + z*w1z;
            outD[(size_t)(base_row + r) * C + t] = db + x*wdx + y*wdy + z*wdz;
        }
    }
    __syncthreads();

    const int w = t >> 5, lane = t & 31;
    unsigned long long acc[4][2];
    if (AN) {
        const float4 bav = ((const float4*)ba)[lane];
#pragma unroll
        for (int r = 0; r < 4; ++r) {
            PACKF2(acc[r][0], bav.x, bav.y);
            PACKF2(acc[r][1], bav.z, bav.w);
        }
    } else {
#pragma unroll
        for (int r = 0; r < 4; ++r) { acc[r][0] = 0ull; acc[r][1] = 0ull; }
    }

    const ulonglong2* WaV = (const ulonglong2*)Wa;   // row cc = 32 ulonglong2
    const float* qrow = q_s + (w * 4) * C;
#pragma unroll 4
    for (int cc = 0; cc < C; ++cc) {
        const ulonglong2 wv = WaV[cc * 32 + lane];
#pragma unroll
        for (int r = 0; r < 4; ++r) {
            const float q = qrow[r * C + cc];
            unsigned long long qq; PACKF2(qq, q, q);
            FFMA2(acc[r][0], qq, wv.x, acc[r][0]);
            FFMA2(acc[r][1], qq, wv.y, acc[r][1]);
        }
    }

    float* outA = AN ? g_QA : g_KA;
#pragma unroll
    for (int r = 0; r < 4; ++r) {
        ulonglong2 st; st.x = acc[r][0]; st.y = acc[r][1];
        ((ulonglong2*)(outA + (size_t)(base_row + w*4 + r) * C))[lane] = st;
    }
}

// ---------------------------------------------------------------------------
// Ball query via grid. Warp per anchor (cell-sorted order). The 3 x-adjacent
// cells are contiguous in g_list after the scan, so the 27-cell neighborhood
// collapses to 9 contiguous spans. Collect hits, then warp rank-sort
// (pairwise '<' counts) for first-KNN-by-original-index semantics.
// ---------------------------------------------------------------------------
__global__ void ballquery_kernel(const float* __restrict__ anchor,
                                 const float* __restrict__ neighbor)
{
    constexpr unsigned FULL = 0xffffffffu;
    constexpr int CAP = 128;
    __shared__ int hbuf[8][CAP];
    __shared__ int sorted[8][KNN];

    const int warp = threadIdx.x >> 5;
    const int lane = threadIdx.x & 31;
    const int p    = blockIdx.x * 8 + warp;       // cell-sorted anchor position
    const int b    = p >> 12;
    const int row  = (b << 12) + g_list[p];       // set 0 region

    const float ax = anchor[(size_t)row*3 + 0];
    const float ay = anchor[(size_t)row*3 + 1];
    const float az = anchor[(size_t)row*3 + 2];
    int cx, cy, cz; cell_coords(ax, ay, az, cx, cy, cz);

    const int nbase = (B + b) * NC;               // set 1 grid region
    const int lbase = (B + b) * 4096;             // set 1 list region
    const float* nb = neighbor + (size_t)b * MPTS * 3;

    const int x0 = max(cx - 1, 0), x1 = min(cx + 1, GC - 1);
    const int z0 = max(cz - 1, 0), z1 = min(cz + 1, GC - 1);
    const int y0 = max(cy - 1, 0), y1 = min(cy + 1, GC - 1);

    int hcnt = 0;
    for (int z = z0; z <= z1; ++z) {
        for (int y = y0; y <= y1; ++y) {
            const int cA = nbase + z*64 + y*8 + x0;
            const int cB = nbase + z*64 + y*8 + x1;
            const int st = g_start[cA];
            const int en = g_start[cB] + g_cnt[cB];
            for (int j = st; j < en; j += 32) {
                const int q = j + lane;
                int m = 0; bool hit = false;
                if (q < en) {
                    m = g_list[lbase + q];
                    const float fx = nb[m*3+0] - ax;
                    const float fy = nb[m*3+1] - ay;
                    const float fz = nb[m*3+2] - az;
                    hit = (fx*fx + fy*fy + fz*fz) < RAD2;
                }
                const unsigned mk = __ballot_sync(FULL, hit);
                if (hit) {
                    const int pos = hcnt + __popc(mk & ((1u << lane) - 1u));
                    if (pos < CAP) hbuf[warp][pos] = m;
                }
                hcnt += __popc(mk);
            }
        }
    }

    __syncwarp(FULL);
    const int n = min(hcnt, CAP);
    const int rounds = (n + 31) >> 5;

    int v[4], rk[4];
#pragma unroll
    for (int r = 0; r < 4; ++r) {
        const int i = lane + 32*r;
        v[r]  = (i < n) ? hbuf[warp][i] : 0x7fffffff;
        rk[r] = 0;
    }
    for (int step = 0; step < 32; ++step) {
#pragma unroll
        for (int s = 0; s < 4; ++s) {
            if (s < rounds) {
                const int u = __shfl_sync(FULL, v[s], step);
#pragma unroll
                for (int r = 0; r < 4; ++r)
                    if (r < rounds) rk[r] += (u < v[r]);
            }
        }
    }
#pragma unroll
    for (int r = 0; r < 4; ++r) {
        const int i = lane + 32*r;
        if (i < n && rk[r] < KNN) sorted[warp][rk[r]] = v[r];
    }
    __syncwarp(FULL);

    const int take  = min(hcnt, KNN);
    const int first = (hcnt > 0) ? sorted[warp][0] : 0;
    g_idx[(size_t)row * KNN + lane] = (lane < take) ? sorted[warp][lane] : first;
}

// ---------------------------------------------------------------------------
// Attention. Warp per anchor (cell-sorted order for gather locality).
// Lane holds channels [4*lane, 4*lane+4). Softmax without max-shift
// (shift-invariant; |logit| <= ~65, no fp32 overflow). Warp sum via 5-step
// shfl_xor butterfly; k-loop unrolled x4 so 4 chains overlap.
// ---------------------------------------------------------------------------
__global__ void attn_kernel(float* __restrict__ out)
{
    constexpr unsigned FULL = 0xffffffffu;
    const int warp = threadIdx.x >> 5;
    const int lane = threadIdx.x & 31;
    const int p    = blockIdx.x * 8 + warp;
    const int b    = p >> 12;
    const int row  = (b << 12) + g_list[p];

    const float4 qa = ((const float4*)(g_QA + (size_t)row * C))[lane];
    const float4 ad = ((const float4*)(g_AD + (size_t)row * C))[lane];
    const int my_m  = g_idx[(size_t)row * KNN + lane];

    const float4* KA4 = (const float4*)(g_KA + (size_t)b * MPTS * C);
    const float4* ND4 = (const float4*)(g_ND + (size_t)b * MPTS * C);

    float4 o = make_float4(-3.4e38f, -3.4e38f, -3.4e38f, -3.4e38f);

#pragma unroll 4
    for (int k = 0; k < KNN; ++k) {
        const int m = __shfl_sync(FULL, my_m, k);
        const float4 kv = KA4[m * 32 + lane];
        const float4 nv = ND4[m * 32 + lane];

        const float e0 = __expf(qa.x - kv.x);
        const float e1 = __expf(qa.y - kv.y);
        const float e2 = __expf(qa.z - kv.z);
        const float e3 = __expf(qa.w - kv.w);

        float s = (e0 + e1) + (e2 + e3);
#pragma unroll
        for (int off = 16; off; off >>= 1)
            s += __shfl_xor_sync(FULL, s, off);

        const float inv = __fdividef(1.0f, s);
        o.x = fmaxf(o.x, (ad.x - nv.x) * (e0 * inv));
        o.y = fmaxf(o.y, (ad.y - nv.y) * (e1 * inv));
        o.z = fmaxf(o.z, (ad.z - nv.z) * (e2 * inv));
        o.w = fmaxf(o.w, (ad.w - nv.w) * (e3 * inv));
    }

    ((float4*)(out + (size_t)row * C))[lane] = o;
}

// ---------------------------------------------------------------------------
// Launch: fork proj onto a side stream (no dependency on the grid), join
// before attn. Streams/events are created lazily on the first (uncaptured)
// correctness call; during capture the record/wait pairs become graph edges.
// ---------------------------------------------------------------------------
extern "C" void kernel_launch(void* const* d_in, const int* in_sizes, int n_in,
                              void* d_out, int out_size)
{
    const float* anchor   = (const float*)d_in[0];
    const float* neighbor = (const float*)d_in[1];
    const float* Wq = (const float*)d_in[2];
    const float* bq = (const float*)d_in[3];
    const float* Wk = (const float*)d_in[4];
    const float* bk = (const float*)d_in[5];
    const float* Wd = (const float*)d_in[6];
    const float* bd = (const float*)d_in[7];
    const float* Wa = (const float*)d_in[8];
    const float* ba = (const float*)d_in[9];
    float* out = (float*)d_out;

    static cudaStream_t s_side = nullptr;
    static cudaEvent_t  e_fork = nullptr, e_join = nullptr;
    if (s_side == nullptr) {
        cudaStreamCreateWithFlags(&s_side, cudaStreamNonBlocking);
        cudaEventCreateWithFlags(&e_fork, cudaEventDisableTiming);
        cudaEventCreateWithFlags(&e_join, cudaEventDisableTiming);
    }

    // Fork: proj runs concurrently with gridbuild + ballquery.
    cudaEventRecord(e_fork, 0);
    cudaStreamWaitEvent(s_side, e_fork, 0);
    proj_kernel<<<2048, 128, 0, s_side>>>(anchor, neighbor,
                                          Wq, bq, Wk, bk, Wd, bd, Wa, ba);
    cudaEventRecord(e_join, s_side);

    gridbuild_kernel<<<8, 512>>>(anchor, neighbor);
    ballquery_kernel<<<2048, 256>>>(anchor, neighbor);

    // Join: attn needs proj outputs + g_idx + g_list.
    cudaStreamWaitEvent(0, e_join, 0);
    attn_kernel<<<2048, 256>>>(out);
}